// round 14
// baseline (speedup 1.0000x reference)
#include <cuda_runtime.h>
#include <cuda_bf16.h>
#include <stdint.h>
#include <math.h>

// ============================================================================
// AttentionLayer via mma.sync (HMMA) bf16 split (hi/lo) GEMMs, fp32 accum.
//   y = softmax((XqW^T+b)(XkW^T+b)^T / 32) (XvW^T+b)
// N=4, S=T=2048, D=1024.  Harness PTX target is plain sm_103 -> no tcgen05.
// R13: 128x256 CTA tile, 64x64 warp tile (smem-crossbar bound -> balanced),
//      occ 1 CTA/SM, BK=64, STAGES=2.
// ============================================================================

#define NBATCH 4
#define SEQ    2048
#define DIM    1024

#define ROWB    144               // 64 bf16 = 128B + 16B pad
#define ROWBT   528               // 256 bf16 = 512B + 16B pad (trans B tiles)
#define STAGEA  (128 * ROWB)      // 18432
#define STAGEBB (256 * ROWB)      // 36864 (>= 64*ROWBT = 33792)
#define SMEM_DYN (2 * STAGEA + 2 * STAGEBB)   // 110592

// ------------------------- scratch (__device__ globals) ---------------------
#define ND ((long long)NBATCH * SEQ * DIM)   // 8,388,608
#define NS ((long long)NBATCH * SEQ * SEQ)   // 16,777,216

__device__ __align__(256) __nv_bfloat16 g_xin_hi[3 * ND], g_xin_lo[3 * ND];
__device__ __align__(256) __nv_bfloat16 g_qkv_hi[3 * ND], g_qkv_lo[3 * ND];
__device__ __align__(256) __nv_bfloat16 g_W_hi[DIM * DIM], g_W_lo[DIM * DIM];
__device__ __align__(256) float         g_s[NS];
__device__ __align__(256) __nv_bfloat16 g_p_hi[NS], g_p_lo[NS];

// ------------------------------ PTX helpers ---------------------------------
__device__ __forceinline__ uint32_t s2u(const void* p) {
    uint32_t a;
    asm("{ .reg .u64 t; cvta.to.shared.u64 t, %1; cvt.u32.u64 %0, t; }"
        : "=r"(a) : "l"(p));
    return a;
}
__device__ __forceinline__ void cp16(uint32_t s, const void* g) {
    asm volatile("cp.async.cg.shared.global [%0], [%1], 16;" :: "r"(s), "l"(g) : "memory");
}
__device__ __forceinline__ void cp_commit() {
    asm volatile("cp.async.commit_group;" ::: "memory");
}
template <int N> __device__ __forceinline__ void cp_wait() {
    asm volatile("cp.async.wait_group %0;" :: "n"(N) : "memory");
}
__device__ __forceinline__ void ldsm4(uint32_t* r, uint32_t a) {
    asm volatile("ldmatrix.sync.aligned.m8n8.x4.shared.b16 {%0,%1,%2,%3}, [%4];"
                 : "=r"(r[0]), "=r"(r[1]), "=r"(r[2]), "=r"(r[3]) : "r"(a));
}
__device__ __forceinline__ void ldsm4t(uint32_t* r, uint32_t a) {
    asm volatile("ldmatrix.sync.aligned.m8n8.x4.trans.shared.b16 {%0,%1,%2,%3}, [%4];"
                 : "=r"(r[0]), "=r"(r[1]), "=r"(r[2]), "=r"(r[3]) : "r"(a));
}
__device__ __forceinline__ void mma16816(float* c, const uint32_t* a,
                                         uint32_t b0, uint32_t b1) {
    asm volatile(
        "mma.sync.aligned.m16n8k16.row.col.f32.bf16.bf16.f32 "
        "{%0,%1,%2,%3},{%4,%5,%6,%7},{%8,%9},{%0,%1,%2,%3};"
        : "+f"(c[0]), "+f"(c[1]), "+f"(c[2]), "+f"(c[3])
        : "r"(a[0]), "r"(a[1]), "r"(a[2]), "r"(a[3]), "r"(b0), "r"(b1));
}

// ------------------------------ GEMM kernel ---------------------------------
// D[m][n] = sum_k A[m][k]*B[n][k] over 3 segments (Ahi*Bhi + Ahi*Blo + Alo*Bhi).
// CTA tile 128 M x 256 N; 8 warps as 2(M) x 4(N), each 64x64; BK=64, 2 stages.
// BT=0: B stored [n][k] row-major (NT).  BT=1: B stored [k][n] (NN, trans ldsm).
// MODE 0: Cf = alpha*acc.  MODE 1: hi/lo bf16 out with bias.
template <int MODE, int BT>
__global__ __launch_bounds__(256, 1)
void gemm_mma(const __nv_bfloat16* __restrict__ Ahi, const __nv_bfloat16* __restrict__ Alo,
              const __nv_bfloat16* __restrict__ Bhi, const __nv_bfloat16* __restrict__ Blo,
              float* __restrict__ Cf, __nv_bfloat16* __restrict__ Chi,
              __nv_bfloat16* __restrict__ Clo, const float* __restrict__ bias,
              float alpha, int K, int lda, int ldb, int ldc,
              long long sA, long long sB, long long sC)
{
    extern __shared__ uint8_t dynsm[];
    const uint32_t smA = s2u(dynsm);
    const uint32_t smB = smA + 2 * STAGEA;

    const int tid = threadIdx.x;
    const int wid = tid >> 5, lane = tid & 31;
    const int wm = wid & 1;            // 2 warp rows of 64
    const int wn = wid >> 1;           // 4 warp cols of 64
    const int m0 = blockIdx.y * 128, n0 = blockIdx.x * 256;
    const int z = blockIdx.z;
    Ahi += (long long)z * sA;  Alo += (long long)z * sA;
    Bhi += (long long)z * sB;  Blo += (long long)z * sB;

    const int kc = K >> 6;             // 64-wide chunks per segment
    const int nch = 3 * kc;
    const __nv_bfloat16* Aseg[3] = { Ahi, Ahi, Alo };
    const __nv_bfloat16* Bseg[3] = { Bhi, Blo, Bhi };

    float acc[4][8][4];
#pragma unroll
    for (int i = 0; i < 4; i++)
#pragma unroll
        for (int j = 0; j < 8; j++)
#pragma unroll
            for (int q = 0; q < 4; q++) acc[i][j][q] = 0.0f;

    auto load = [&](int c) {
        const int st = c & 1;
        const int seg = c / kc;
        const int kk = (c - seg * kc) << 6;
        const __nv_bfloat16* Ap = Aseg[seg];
        const __nv_bfloat16* Bp = Bseg[seg];
        const uint32_t sa = smA + st * STAGEA;
        const uint32_t sb = smB + st * STAGEBB;
        // A tile: 128 rows x 128B (1024 x 16B, 4/thread)
#pragma unroll
        for (int i = 0; i < 4; i++) {
            const int idx = tid + i * 256;
            const int row = idx >> 3, cg = idx & 7;
            cp16(sa + row * ROWB + cg * 16,
                 Ap + (long long)(m0 + row) * lda + kk + cg * 8);
        }
        if (BT) {
            // B tile: v[kk..kk+64][n0..n0+256] = 64 rows x 512B (2048 x 16B, 8/thread)
#pragma unroll
            for (int i = 0; i < 8; i++) {
                const int idx = tid + i * 256;
                const int row = idx >> 5, cg = idx & 31;
                cp16(sb + row * ROWBT + cg * 16,
                     Bp + (long long)(kk + row) * ldb + n0 + cg * 8);
            }
        } else {
            // B tile: 256 rows x 128B (2048 x 16B, 8/thread)
#pragma unroll
            for (int i = 0; i < 8; i++) {
                const int idx = tid + i * 256;
                const int row = idx >> 3, cg = idx & 7;
                cp16(sb + row * ROWB + cg * 16,
                     Bp + (long long)(n0 + row) * ldb + kk + cg * 8);
            }
        }
        cp_commit();
    };

    load(0);

    const int lrow16 = lane & 15;              // ldmatrix row within 16
    const int lhalf = lane >> 4;

    for (int c = 0; c < nch; c++) {
        cp_wait<0>();
        __syncthreads();
        if (c + 1 < nch) load(c + 1);

        const uint32_t stA = smA + (c & 1) * STAGEA;
        const uint32_t stB = smB + (c & 1) * STAGEBB;
#pragma unroll
        for (int ks = 0; ks < 4; ks++) {
            uint32_t a[4][4], b[4][4];
#pragma unroll
            for (int mt = 0; mt < 4; mt++)
                ldsm4(a[mt], stA + (wm * 64 + mt * 16 + lrow16) * ROWB
                                 + ks * 32 + lhalf * 16);
            if (BT) {
#pragma unroll
                for (int pair = 0; pair < 4; pair++)
                    ldsm4t(b[pair], stB + (ks * 16 + lrow16) * ROWBT
                                        + (wn * 64 + pair * 16 + lhalf * 8) * 2);
#pragma unroll
                for (int mt = 0; mt < 4; mt++)
#pragma unroll
                    for (int nt = 0; nt < 8; nt++)
                        mma16816(acc[mt][nt], a[mt],
                                 b[nt >> 1][(nt & 1) * 2],
                                 b[nt >> 1][(nt & 1) * 2 + 1]);
            } else {
#pragma unroll
                for (int pair = 0; pair < 4; pair++)
                    ldsm4(b[pair], stB + (wn * 64 + pair * 16 + lrow16) * ROWB
                                       + ks * 32 + lhalf * 16);
#pragma unroll
                for (int mt = 0; mt < 4; mt++)
#pragma unroll
                    for (int nt = 0; nt < 8; nt++)
                        mma16816(acc[mt][nt], a[mt],
                                 b[nt >> 1][nt & 1],
                                 b[nt >> 1][2 + (nt & 1)]);
            }
        }
    }

    // ------------------------------- epilogue -------------------------------
    const int qr = lane >> 2;          // row within 8
    const int qc = (lane & 3) * 2;     // col pair
#pragma unroll
    for (int mt = 0; mt < 4; mt++) {
        const int mA = m0 + wm * 64 + mt * 16 + qr;
#pragma unroll
        for (int nt = 0; nt < 8; nt++) {
            const int n = n0 + wn * 64 + nt * 8 + qc;
            const float* a4 = acc[mt][nt];
            if (MODE == 0) {
                float* base = Cf + (long long)z * sC;
                float2 s0 = { alpha * a4[0], alpha * a4[1] };
                float2 s1 = { alpha * a4[2], alpha * a4[3] };
                *(float2*)&base[(long long)mA * ldc + n] = s0;
                *(float2*)&base[(long long)(mA + 8) * ldc + n] = s1;
            } else {
                const float b0 = __ldg(&bias[n]), b1 = __ldg(&bias[n + 1]);
                __nv_bfloat16* oh = Chi + (long long)z * sC;
                __nv_bfloat16* ol = Clo + (long long)z * sC;
#pragma unroll
                for (int h = 0; h < 2; h++) {
                    const long long r = (long long)(mA + h * 8) * ldc + n;
                    const float o0 = a4[h * 2 + 0] + b0;
                    const float o1 = a4[h * 2 + 1] + b1;
                    const __nv_bfloat16 h0 = __float2bfloat16(o0);
                    const __nv_bfloat16 h1 = __float2bfloat16(o1);
                    *(uint32_t*)&oh[r] =
                        (uint32_t)*(const uint16_t*)&h0 |
                        ((uint32_t)*(const uint16_t*)&h1 << 16);
                    const __nv_bfloat16 l0 = __float2bfloat16(o0 - __bfloat162float(h0));
                    const __nv_bfloat16 l1 = __float2bfloat16(o1 - __bfloat162float(h1));
                    *(uint32_t*)&ol[r] =
                        (uint32_t)*(const uint16_t*)&l0 |
                        ((uint32_t)*(const uint16_t*)&l1 << 16);
                }
            }
        }
    }
}

// ------------------ fp32 -> hi/lo split (q,k,v,W in one launch) -------------
__global__ __launch_bounds__(256) void split_all(
    const float4* __restrict__ q, const float4* __restrict__ k,
    const float4* __restrict__ v, const float4* __restrict__ w,
    uint2* __restrict__ xhi, uint2* __restrict__ xlo,
    uint2* __restrict__ whi, uint2* __restrict__ wlo, int n4, int n4w)
{
    const int z = blockIdx.z;
    const float4* src;
    uint2 *hi, *lo;
    int n;
    if (z < 3) {
        src = (z == 0) ? q : (z == 1) ? k : v;
        hi = xhi + (long long)z * (ND / 4);
        lo = xlo + (long long)z * (ND / 4);
        n = n4;
    } else {
        src = w; hi = whi; lo = wlo; n = n4w;
    }
    for (int i = blockIdx.x * blockDim.x + threadIdx.x; i < n;
         i += gridDim.x * blockDim.x) {
        const float4 val = src[i];
        __align__(8) __nv_bfloat16 h[4], l[4];
        const float vv[4] = { val.x, val.y, val.z, val.w };
#pragma unroll
        for (int j = 0; j < 4; j++) {
            const __nv_bfloat16 hh = __float2bfloat16(vv[j]);
            h[j] = hh;
            l[j] = __float2bfloat16(vv[j] - __bfloat162float(hh));
        }
        hi[i] = *(const uint2*)h;
        lo[i] = *(const uint2*)l;
    }
}

// -------------- row softmax over T=2048, emits hi/lo bf16 probs -------------
__global__ __launch_bounds__(256) void softmax_rows(const float* __restrict__ S,
                                                    __nv_bfloat16* __restrict__ Phi,
                                                    __nv_bfloat16* __restrict__ Plo)
{
    const long long row = (long long)blockIdx.x * SEQ;
    const float* p = S + row;
    const int tid = threadIdx.x;
    const int lane = tid & 31, wid = tid >> 5;

    float v[8];
    *(float4*)&v[0] = *(const float4*)&p[tid * 8];
    *(float4*)&v[4] = *(const float4*)&p[tid * 8 + 4];

    __shared__ float red[8];
    float m = v[0];
#pragma unroll
    for (int i = 1; i < 8; i++) m = fmaxf(m, v[i]);
#pragma unroll
    for (int o = 16; o > 0; o >>= 1) m = fmaxf(m, __shfl_xor_sync(0xffffffffu, m, o));
    if (lane == 0) red[wid] = m;
    __syncthreads();
    m = red[0];
#pragma unroll
    for (int i = 1; i < 8; i++) m = fmaxf(m, red[i]);
    __syncthreads();

    float s = 0.0f;
#pragma unroll
    for (int i = 0; i < 8; i++) { v[i] = expf(v[i] - m); s += v[i]; }
#pragma unroll
    for (int o = 16; o > 0; o >>= 1) s += __shfl_xor_sync(0xffffffffu, s, o);
    if (lane == 0) red[wid] = s;
    __syncthreads();
    s = 0.0f;
#pragma unroll
    for (int i = 0; i < 8; i++) s += red[i];
    const float inv = 1.0f / s;

    __align__(16) __nv_bfloat16 h[8], l[8];
#pragma unroll
    for (int i = 0; i < 8; i++) {
        const float o = v[i] * inv;
        const __nv_bfloat16 hh = __float2bfloat16(o);
        h[i] = hh;
        l[i] = __float2bfloat16(o - __bfloat162float(hh));
    }
    *(uint4*)(Phi + row + tid * 8) = *(const uint4*)h;
    *(uint4*)(Plo + row + tid * 8) = *(const uint4*)l;
}

// --------------------------------- launch -----------------------------------
extern "C" void kernel_launch(void* const* d_in, const int* in_sizes, int n_in,
                              void* d_out, int out_size)
{
    const float* q_in = (const float*)d_in[0];
    const float* k_in = (const float*)d_in[1];
    const float* v_in = (const float*)d_in[2];
    const float* W    = (const float*)d_in[3];
    const float* bias = (const float*)d_in[4];
    float* out = (float*)d_out;

    __nv_bfloat16 *xin_hi, *xin_lo, *qkv_hi, *qkv_lo, *w_hi, *w_lo, *p_hi, *p_lo;
    float* sbuf;
    cudaGetSymbolAddress((void**)&xin_hi, g_xin_hi);
    cudaGetSymbolAddress((void**)&xin_lo, g_xin_lo);
    cudaGetSymbolAddress((void**)&qkv_hi, g_qkv_hi);
    cudaGetSymbolAddress((void**)&qkv_lo, g_qkv_lo);
    cudaGetSymbolAddress((void**)&w_hi,  g_W_hi);
    cudaGetSymbolAddress((void**)&w_lo,  g_W_lo);
    cudaGetSymbolAddress((void**)&p_hi,  g_p_hi);
    cudaGetSymbolAddress((void**)&p_lo,  g_p_lo);
    cudaGetSymbolAddress((void**)&sbuf,  g_s);

    cudaFuncSetAttribute(gemm_mma<0, 0>, cudaFuncAttributeMaxDynamicSharedMemorySize, SMEM_DYN);
    cudaFuncSetAttribute(gemm_mma<1, 0>, cudaFuncAttributeMaxDynamicSharedMemorySize, SMEM_DYN);
    cudaFuncSetAttribute(gemm_mma<0, 1>, cudaFuncAttributeMaxDynamicSharedMemorySize, SMEM_DYN);

    // one split launch for q,k,v (z<3) and W (z=3)
    {
        dim3 g(256, 1, 4);
        split_all<<<g, 256>>>((const float4*)q_in, (const float4*)k_in,
                              (const float4*)v_in, (const float4*)W,
                              (uint2*)xin_hi, (uint2*)xin_lo,
                              (uint2*)w_hi, (uint2*)w_lo,
                              (int)(ND / 4), DIM * DIM / 4);
    }

    // Projections (q,k,v in one launch via z): [8192,1024] = X @ W^T + b
    {
        dim3 g(DIM / 256, (NBATCH * SEQ) / 128, 3);
        gemm_mma<1, 0><<<g, 256, SMEM_DYN>>>(xin_hi, xin_lo, w_hi, w_lo,
                                             nullptr, qkv_hi, qkv_lo, bias, 1.0f,
                                             DIM, DIM, DIM, DIM, ND, 0, ND);
    }

    const __nv_bfloat16* q_hi = qkv_hi;          const __nv_bfloat16* q_lo = qkv_lo;
    const __nv_bfloat16* k_hi = qkv_hi + ND;     const __nv_bfloat16* k_lo = qkv_lo + ND;
    const __nv_bfloat16* v_hi = qkv_hi + 2 * ND; const __nv_bfloat16* v_lo = qkv_lo + 2 * ND;

    // Scores: S[n] = (q[n] @ k[n]^T) / 32
    {
        dim3 g(SEQ / 256, SEQ / 128, NBATCH);
        gemm_mma<0, 0><<<g, 256, SMEM_DYN>>>(q_hi, q_lo, k_hi, k_lo,
                                             sbuf, nullptr, nullptr, nullptr,
                                             1.0f / 32.0f, DIM, DIM, DIM, SEQ,
                                             (long long)SEQ * DIM, (long long)SEQ * DIM,
                                             (long long)SEQ * SEQ);
    }

    // Softmax -> hi/lo probs
    softmax_rows<<<NBATCH * SEQ, 256>>>(sbuf, p_hi, p_lo);

    // PV: y[n] = P[n] @ v[n]; v row-major [t][d] consumed via ldmatrix.trans
    {
        dim3 g(DIM / 256, SEQ / 128, NBATCH);
        gemm_mma<0, 1><<<g, 256, SMEM_DYN>>>(p_hi, p_lo, v_hi, v_lo,
                                             out, nullptr, nullptr, nullptr,
                                             1.0f, SEQ, SEQ, DIM, DIM,
                                             (long long)SEQ * SEQ, (long long)SEQ * DIM,
                                             (long long)SEQ * DIM);
    }
}